// round 13
// baseline (speedup 1.0000x reference)
#include <cuda_runtime.h>
#include <cuda_bf16.h>
#include <cuda_fp16.h>
#include <cstdint>

#define B_DIM 4096
#define D_DIM 1024
#define D_PK  512          // packed fp8 pairs per row (uint16 units)
#define K_DIM 3000
#define KC8   375          // K_DIM / 8 : 16B chunks per 16-bit row
#define KP    3008
#define IEPS  20.0f
#define ITMP  10.0f
#define TEMP  0.1f
#define EPIT  132          // epilogue smem pitch (floats)

// ---------------- scratch ----------------
__device__ __align__(256) __nv_bfloat16  g_scores[2][(size_t)B_DIM * K_DIM]; // 49.2 MB (s)
__device__ __align__(256) __half         g_M[2][(size_t)B_DIM * K_DIM];      // 49.2 MB (exp(s/eps))
__device__ __align__(256) uint16_t       g_z8[2][(size_t)B_DIM * D_PK];      //  8.4 MB
__device__ __align__(256) uint16_t       g_W8[(size_t)K_DIM * D_PK];         //  3.1 MB
__device__ __align__(256) float          g_c [2][3][KP];
__device__ __align__(256) float          g_p [2][3][B_DIM];
__device__ __align__(256) float          g_E [2][B_DIM];
__device__ __align__(256) float          g_t [2][B_DIM];

// ---------------- helpers ----------------
__device__ __forceinline__ float warp_red(float v) {
    #pragma unroll
    for (int o = 16; o; o >>= 1) v += __shfl_xor_sync(0xffffffffu, v, o);
    return v;
}
__device__ __forceinline__ float frcp(float x) {
    float r; asm("rcp.approx.f32 %0, %1;" : "=f"(r) : "f"(x)); return r;
}
__device__ __forceinline__ void unpack8h(uint4 ch, float* f) {
    __half2* h = reinterpret_cast<__half2*>(&ch);
    #pragma unroll
    for (int k = 0; k < 4; k++) {
        float2 t = __half22float2(h[k]);
        f[2 * k] = t.x; f[2 * k + 1] = t.y;
    }
}
__device__ __forceinline__ void unpack8b(uint4 ch, float* f) {
    __nv_bfloat162* h = reinterpret_cast<__nv_bfloat162*>(&ch);
    #pragma unroll
    for (int k = 0; k < 4; k++) {
        float2 t = __bfloat1622float2(h[k]);
        f[2 * k] = t.x; f[2 * k + 1] = t.y;
    }
}
__device__ __forceinline__ uint16_t pk2(float f0, float f1) {
    uint16_t r;
    asm("cvt.rn.satfinite.e4m3x2.f32 %0, %2, %1;" : "=h"(r) : "f"(f0), "f"(f1));
    return r;
}
__device__ __forceinline__ uint32_t pk4(float f0, float f1, float f2, float f3) {
    return (uint32_t)pk2(f0, f1) | ((uint32_t)pk2(f2, f3) << 16);
}

// ---------------- cvt (fp32 -> e4m3 inputs) + init ----------------
__global__ void cvt_kernel(const float* __restrict__ z1,
                           const float* __restrict__ z2,
                           const float* __restrict__ W) {
    const int n8 = B_DIM * D_DIM / 8;
    const int nw8 = K_DIM * D_DIM / 8;
    int idx0 = blockIdx.x * blockDim.x + threadIdx.x;
    if (idx0 < 2 * 3 * KP)  ((float*)g_c)[idx0] = 0.0f;
    if (idx0 < 2 * B_DIM)   ((float*)g_E)[idx0] = 0.0f;
    int stride = gridDim.x * blockDim.x;
    for (int i = idx0; i < n8; i += stride) {
        float4 a = reinterpret_cast<const float4*>(z1)[i * 2];
        float4 b = reinterpret_cast<const float4*>(z1)[i * 2 + 1];
        uint2 o;
        o.x = pk4(a.x, a.y, a.z, a.w);
        o.y = pk4(b.x, b.y, b.z, b.w);
        reinterpret_cast<uint2*>(g_z8[0])[i] = o;
        a = reinterpret_cast<const float4*>(z2)[i * 2];
        b = reinterpret_cast<const float4*>(z2)[i * 2 + 1];
        o.x = pk4(a.x, a.y, a.z, a.w);
        o.y = pk4(b.x, b.y, b.z, b.w);
        reinterpret_cast<uint2*>(g_z8[1])[i] = o;
        if (i < nw8) {
            a = reinterpret_cast<const float4*>(W)[i * 2];
            b = reinterpret_cast<const float4*>(W)[i * 2 + 1];
            o.x = pk4(a.x, a.y, a.z, a.w);
            o.y = pk4(b.x, b.y, b.z, b.w);
            reinterpret_cast<uint2*>(g_W8)[i] = o;
        }
    }
}

// ---------------- GEMM: mma.sync fp8 e4m3, 128x128 tile, 3-stage cp.async ----------------
#define STAGE_ELEMS 5120
#define LDT 40
#define NKT 16
#define DYN_SMEM 69632

__device__ __forceinline__ void cp16(void* sdst, const void* gsrc) {
    uint32_t s = (uint32_t)__cvta_generic_to_shared(sdst);
    asm volatile("cp.async.cg.shared.global [%0], [%1], 16;" :: "r"(s), "l"(gsrc));
}

#define LDSM4(R0,R1,R2,R3,ADDR) \
    asm volatile("ldmatrix.sync.aligned.m8n8.x4.shared.b16 {%0,%1,%2,%3}, [%4];" \
                 : "=r"(R0), "=r"(R1), "=r"(R2), "=r"(R3) : "r"(ADDR))

__device__ __forceinline__ void mma16832(float* c, const uint32_t* a, const uint32_t* b) {
    asm volatile(
        "mma.sync.aligned.m16n8k32.row.col.f32.e4m3.e4m3.f32 "
        "{%0,%1,%2,%3}, {%4,%5,%6,%7}, {%8,%9}, {%0,%1,%2,%3};"
        : "+f"(c[0]), "+f"(c[1]), "+f"(c[2]), "+f"(c[3])
        : "r"(a[0]), "r"(a[1]), "r"(a[2]), "r"(a[3]), "r"(b[0]), "r"(b[1]));
}

__device__ __forceinline__ void load_stage(uint16_t* As, uint16_t* Bs,
                                           const uint16_t* Ag, int n_base,
                                           int s, int kt, int tid) {
    #pragma unroll
    for (int h = 0; h < 2; h++) {
        int c = tid + h * 256;
        int r = c >> 2, c16 = c & 3;
        cp16(As + s * STAGE_ELEMS + r * LDT + c16 * 8,
             Ag + (size_t)r * D_PK + kt * 32 + c16 * 8);
    }
    #pragma unroll
    for (int h = 0; h < 2; h++) {
        int c = tid + h * 256;
        int r = c >> 2, c16 = c & 3;
        int gn = n_base + r; if (gn >= K_DIM) gn = K_DIM - 1;
        cp16(Bs + s * STAGE_ELEMS + r * LDT + c16 * 8,
             g_W8 + (size_t)gn * D_PK + kt * 32 + c16 * 8);
    }
    asm volatile("cp.async.commit_group;");
}

__global__ void __launch_bounds__(256, 2) gemm_kernel() {
    extern __shared__ char smem_raw[];
    uint16_t* As = reinterpret_cast<uint16_t*>(smem_raw);
    uint16_t* Bs = As + 3 * STAGE_ELEMS;
    float* epi = reinterpret_cast<float*>(smem_raw);

    const int tid = threadIdx.x;
    const int bn = blockIdx.x, bm = blockIdx.y, mat = blockIdx.z;
    const uint16_t* Ag = g_z8[mat] + (size_t)bm * 128 * D_PK;
    const int n_base = bn * 128;

    load_stage(As, Bs, Ag, n_base, 0, 0, tid);
    load_stage(As, Bs, Ag, n_base, 1, 1, tid);

    float acc[2][8][4];
    #pragma unroll
    for (int a = 0; a < 2; a++)
        #pragma unroll
        for (int b = 0; b < 8; b++)
            #pragma unroll
            for (int c = 0; c < 4; c++) acc[a][b][c] = 0.0f;

    const int lane = tid & 31, wid = tid >> 5;
    const int wm = wid & 3, wn = wid >> 2;

    for (int kt = 0; kt < NKT; kt++) {
        if (kt == NKT - 1) asm volatile("cp.async.wait_group 0;");
        else               asm volatile("cp.async.wait_group 1;");
        __syncthreads();
        if (kt + 2 < NKT) load_stage(As, Bs, Ag, n_base, (kt + 2) % 3, kt + 2, tid);
        const int cur = kt % 3;
        uint32_t a_base = (uint32_t)__cvta_generic_to_shared(As + cur * STAGE_ELEMS);
        uint32_t b_base = (uint32_t)__cvta_generic_to_shared(Bs + cur * STAGE_ELEMS);
        #pragma unroll
        for (int ks = 0; ks < 2; ks++) {
            uint32_t af[2][4];
            #pragma unroll
            for (int mt = 0; mt < 2; mt++) {
                int row = wm * 32 + mt * 16 + (lane & 15);
                int col = ks * 16 + (lane >> 4) * 8;
                uint32_t ad = a_base + (uint32_t)(row * LDT + col) * 2;
                LDSM4(af[mt][0], af[mt][1], af[mt][2], af[mt][3], ad);
            }
            uint32_t bfr[8][2];
            #pragma unroll
            for (int np = 0; np < 4; np++) {
                int mi = lane >> 3;
                int nr = wn * 64 + np * 16 + (mi >> 1) * 8 + (lane & 7);
                int kc = ks * 16 + (mi & 1) * 8;
                uint32_t ad = b_base + (uint32_t)(nr * LDT + kc) * 2;
                uint32_t r0, r1, r2, r3;
                LDSM4(r0, r1, r2, r3, ad);
                bfr[np * 2][0] = r0; bfr[np * 2][1] = r1;
                bfr[np * 2 + 1][0] = r2; bfr[np * 2 + 1][1] = r3;
            }
            #pragma unroll
            for (int mt = 0; mt < 2; mt++)
                #pragma unroll
                for (int nt = 0; nt < 8; nt++)
                    mma16832(acc[mt][nt], af[mt], bfr[nt]);
        }
    }
    __syncthreads();

    // ---- epilogue: stage fp32 into smem [128][EPIT] ----
    #pragma unroll
    for (int mt = 0; mt < 2; mt++) {
        #pragma unroll
        for (int nt = 0; nt < 8; nt++) {
            int r = wm * 32 + mt * 16 + (lane >> 2);
            int cb = wn * 64 + nt * 8 + 2 * (lane & 3);
            epi[r * EPIT + cb]           = acc[mt][nt][0];
            epi[r * EPIT + cb + 1]       = acc[mt][nt][1];
            epi[(r + 8) * EPIT + cb]     = acc[mt][nt][2];
            epi[(r + 8) * EPIT + cb + 1] = acc[mt][nt][3];
        }
    }
    __syncthreads();

    int nvalid = K_DIM - n_base; if (nvalid > 128) nvalid = 128;   // 128 or 56

    // full-warp epilogue: lane handles 4 columns; ONE exp per element:
    //   e = exp(s/T);  E += e;  M = e*e = exp(s/eps)
    {
        int c4 = lane * 4;
        int g0 = n_base + c4;
        bool act = (c4 < nvalid);
        float colacc[4] = {0.f, 0.f, 0.f, 0.f};
        for (int r = wid * 16; r < wid * 16 + 16; r++) {
            int gi = bm * 128 + r;
            float esum = 0.0f;
            if (act) {
                float4 f = *reinterpret_cast<float4*>(&epi[r * EPIT + c4]);
                __nv_bfloat162 b0 = __floats2bfloat162_rn(f.x, f.y);
                __nv_bfloat162 b1 = __floats2bfloat162_rn(f.z, f.w);
                uint2 os;
                os.x = *reinterpret_cast<uint32_t*>(&b0);
                os.y = *reinterpret_cast<uint32_t*>(&b1);
                *reinterpret_cast<uint2*>(g_scores[mat] + (size_t)gi * K_DIM + g0) = os;
                float e0 = __expf(f.x * ITMP), e1 = __expf(f.y * ITMP);
                float e2 = __expf(f.z * ITMP), e3 = __expf(f.w * ITMP);
                esum = (e0 + e1) + (e2 + e3);
                float m0 = e0 * e0, m1 = e1 * e1, m2 = e2 * e2, m3 = e3 * e3;
                colacc[0] += m0; colacc[1] += m1; colacc[2] += m2; colacc[3] += m3;
                __half2 h0 = __floats2half2_rn(m0, m1);
                __half2 h1 = __floats2half2_rn(m2, m3);
                uint2 om;
                om.x = *reinterpret_cast<uint32_t*>(&h0);
                om.y = *reinterpret_cast<uint32_t*>(&h1);
                *reinterpret_cast<uint2*>(g_M[mat] + (size_t)gi * K_DIM + g0) = om;
            }
            esum = warp_red(esum);
            if (lane == 0) atomicAdd(&g_E[mat][gi], esum);
        }
        if (act) {
            #pragma unroll
            for (int k = 0; k < 4; k++)
                atomicAdd(&g_c[mat][0][g0 + k], colacc[k]);
        }
    }
}

// ---------------- fused sinkhorn iteration: smem-tiled, 16 rows/block ----------------
// smem layout: [0,12032) sv | [12032,108032) tile 16x3000 fp16 (pitch 6000B) | sp
#define FP_TILE_OFF 12032
#define FP_SP_OFF   108032
#define FP_SMEM     108096

__global__ void __launch_bounds__(256) fused_pass(int iter) {
    extern __shared__ char fsm[];
    float* sv = reinterpret_cast<float*>(fsm);
    char*  tile = fsm + FP_TILE_OFF;
    float* sp = reinterpret_cast<float*>(fsm + FP_SP_OFF);
    const int mat = blockIdx.y;
    const int r0 = blockIdx.x * 16;
    const int tid = threadIdx.x;

    // issue tile fill first (cp.async: 16 rows x 375 16B-chunks)
    for (int ch = tid; ch < 16 * KC8; ch += 256) {
        int r = ch / KC8, c = ch - r * KC8;
        cp16(tile + r * 6000 + c * 16,
             reinterpret_cast<const char*>(g_M[mat] + (size_t)(r0 + r) * K_DIM) + c * 16);
    }
    asm volatile("cp.async.commit_group;");

    // sv prologue overlaps the fill
    {
        const float4* c4 = reinterpret_cast<const float4*>(g_c[mat][iter]);
        for (int j4 = tid; j4 < KP / 4; j4 += 256) {
            float4 c = c4[j4];
            reinterpret_cast<float4*>(sv)[j4] =
                make_float4(frcp(c.x), frcp(c.y), frcp(c.z), frcp(c.w));
        }
    }
    asm volatile("cp.async.wait_group 0;");
    __syncthreads();

    const int wid = tid >> 5, lane = tid & 31;

    // phase A: row sums from smem (warp handles 2 rows)
    #pragma unroll
    for (int rr = wid * 2; rr < wid * 2 + 2; rr++) {
        const uint4* mrow = reinterpret_cast<const uint4*>(tile + rr * 6000);
        float acc = 0.0f;
        #pragma unroll 4
        for (int idx = lane; idx < KC8; idx += 32) {
            uint4 ch = mrow[idx];
            float m[8]; unpack8h(ch, m);
            float4 v0 = *reinterpret_cast<const float4*>(&sv[idx * 8]);
            float4 v1 = *reinterpret_cast<const float4*>(&sv[idx * 8 + 4]);
            acc += m[0] * v0.x + m[1] * v0.y + m[2] * v0.z + m[3] * v0.w
                 + m[4] * v1.x + m[5] * v1.y + m[6] * v1.z + m[7] * v1.w;
        }
        acc = warp_red(acc);
        if (lane == 0) {
            float p = acc * (1.0f / (float)K_DIM);
            sp[rr] = frcp(p) * (1.0f / (float)B_DIM);   // u_i
        }
    }
    __syncthreads();

    // phase B: column partials from smem
    float* cn = g_c[mat][iter + 1];
    for (int c8 = tid; c8 < KC8; c8 += 256) {
        float a[8];
        #pragma unroll
        for (int k = 0; k < 8; k++) a[k] = 0.0f;
        #pragma unroll 4
        for (int r = 0; r < 16; r++) {
            uint4 ch = *(reinterpret_cast<const uint4*>(tile + r * 6000) + c8);
            float m[8]; unpack8h(ch, m);
            float u = sp[r];
            #pragma unroll
            for (int k = 0; k < 8; k++) a[k] += m[k] * u;
        }
        #pragma unroll
        for (int k = 0; k < 8; k++)
            atomicAdd(&cn[c8 * 8 + k], a[k]);
    }
}

// ---------------- iter-2 row pass + cross terms (R12 body): grid (256,2) ----------------
__global__ void __launch_bounds__(256) rowcross_kernel() {
    const int m = blockIdx.y, o = 1 - m;
    const int r0 = blockIdx.x * 16;
    __shared__ float sv[KP];
    {
        const float4* c4 = reinterpret_cast<const float4*>(g_c[m][2]);
        for (int j4 = threadIdx.x; j4 < KP / 4; j4 += 256) {
            float4 c = c4[j4];
            *reinterpret_cast<float4*>(&sv[j4 * 4]) =
                make_float4(frcp(c.x), frcp(c.y), frcp(c.z), frcp(c.w));
        }
    }
    __syncthreads();
    const int wid = threadIdx.x >> 5, lane = threadIdx.x & 31;
    for (int rr = wid; rr < 16; rr += 8) {
        int i = r0 + rr;
        const uint4* mrow = reinterpret_cast<const uint4*>(g_M[m] + (size_t)i * K_DIM);
        const uint4* srow = reinterpret_cast<const uint4*>(g_scores[o] + (size_t)i * K_DIM);
        float ap = 0.0f, at = 0.0f;
        #pragma unroll
        for (int t0 = 0; t0 < 12; t0 += 3) {
            uint4 mb[3], sb[3];
            #pragma unroll
            for (int t = 0; t < 3; t++) {
                int idx = lane + (t0 + t) * 32;
                if (idx < KC8) { mb[t] = mrow[idx]; sb[t] = srow[idx]; }
            }
            #pragma unroll
            for (int t = 0; t < 3; t++) {
                int idx = lane + (t0 + t) * 32;
                if (idx < KC8) {
                    float mm[8], x[8];
                    unpack8h(mb[t], mm); unpack8b(sb[t], x);
                    float4 v0 = *reinterpret_cast<const float4*>(&sv[idx * 8]);
                    float4 v1 = *reinterpret_cast<const float4*>(&sv[idx * 8 + 4]);
                    float vv[8] = {v0.x, v0.y, v0.z, v0.w, v1.x, v1.y, v1.z, v1.w};
                    #pragma unroll
                    for (int k = 0; k < 8; k++) {
                        float e = mm[k] * vv[k];
                        ap += e;
                        at += e * x[k];
                    }
                }
            }
        }
        ap = warp_red(ap); at = warp_red(at);
        if (lane == 0) {
            g_p[m][2][i] = ap * (1.0f / (float)K_DIM);
            g_t[m][i]    = at * (1.0f / (float)K_DIM);
        }
    }
}

// ---------------- finalize ----------------
__global__ void finalize_kernel(float* out) {
    float a = 0.0f, l = 0.0f;
    for (int i = threadIdx.x; i < B_DIM; i += blockDim.x) {
        a += g_t[0][i] / ((float)B_DIM * g_p[0][2][i])
           + g_t[1][i] / ((float)B_DIM * g_p[1][2][i]);
        l += __logf(g_E[0][i]) + __logf(g_E[1][i]);
    }
    a = warp_red(a); l = warp_red(l);
    __shared__ float sa[8], sl[8];
    int lane = threadIdx.x & 31, wid = threadIdx.x >> 5;
    if (lane == 0) { sa[wid] = a; sl[wid] = l; }
    __syncthreads();
    if (threadIdx.x == 0) {
        float ta = 0.f, tl = 0.f;
        for (int w = 0; w < 8; w++) { ta += sa[w]; tl += sl[w]; }
        float loss = -0.5f * (ta / ((float)B_DIM * TEMP)
                              - tl / ((float)B_DIM * (float)B_DIM));
        out[0] = loss;
    }
}

// ---------------- launch (single stream) ----------------
extern "C" void kernel_launch(void* const* d_in, const int* in_sizes, int n_in,
                              void* d_out, int out_size) {
    const float* z1 = (const float*)d_in[0];
    const float* z2 = (const float*)d_in[1];
    const float* W  = (const float*)d_in[2];
    float* out = (float*)d_out;

    cudaFuncSetAttribute(gemm_kernel, cudaFuncAttributeMaxDynamicSharedMemorySize, DYN_SMEM);
    cudaFuncSetAttribute(fused_pass, cudaFuncAttributeMaxDynamicSharedMemorySize, FP_SMEM);

    cvt_kernel<<<2048, 256>>>(z1, z2, W);

    dim3 ggrid(24, 32, 2);
    gemm_kernel<<<ggrid, 256, DYN_SMEM>>>();

    fused_pass<<<dim3(256, 2), 256, FP_SMEM>>>(0);   // p0 + c1
    fused_pass<<<dim3(256, 2), 256, FP_SMEM>>>(1);   // p1 + c2
    rowcross_kernel<<<dim3(256, 2), 256>>>();        // p2 + t
    finalize_kernel<<<1, 256>>>(out);
}

// round 14
// speedup vs baseline: 1.0223x; 1.0223x over previous
#include <cuda_runtime.h>
#include <cuda_bf16.h>
#include <cuda_fp16.h>
#include <cstdint>

#define B_DIM 4096
#define D_DIM 1024
#define D_PK  512          // packed fp8 pairs per row (uint16 units)
#define K_DIM 3000
#define KC8   375          // K_DIM / 8 : 16B chunks per 16-bit row
#define KP    3008
#define IEPS  20.0f
#define ITMP  10.0f
#define TEMP  0.1f
#define EPIT  132          // epilogue smem pitch (floats)

// ---------------- scratch ----------------
__device__ __align__(256) __nv_bfloat16  g_scores[2][(size_t)B_DIM * K_DIM]; // 49.2 MB (s)
__device__ __align__(256) __half         g_M[2][(size_t)B_DIM * K_DIM];      // 49.2 MB (exp(s/eps))
__device__ __align__(256) uint16_t       g_z8[2][(size_t)B_DIM * D_PK];      //  8.4 MB
__device__ __align__(256) uint16_t       g_W8[(size_t)K_DIM * D_PK];         //  3.1 MB
__device__ __align__(256) float          g_c [2][3][KP];
__device__ __align__(256) float          g_p [2][3][B_DIM];
__device__ __align__(256) float          g_E [2][B_DIM];
__device__ __align__(256) float          g_t [2][B_DIM];

// ---------------- helpers ----------------
__device__ __forceinline__ float warp_red(float v) {
    #pragma unroll
    for (int o = 16; o; o >>= 1) v += __shfl_xor_sync(0xffffffffu, v, o);
    return v;
}
__device__ __forceinline__ float frcp(float x) {
    float r; asm("rcp.approx.f32 %0, %1;" : "=f"(r) : "f"(x)); return r;
}
__device__ __forceinline__ void unpack8h(uint4 ch, float* f) {
    __half2* h = reinterpret_cast<__half2*>(&ch);
    #pragma unroll
    for (int k = 0; k < 4; k++) {
        float2 t = __half22float2(h[k]);
        f[2 * k] = t.x; f[2 * k + 1] = t.y;
    }
}
__device__ __forceinline__ void unpack8b(uint4 ch, float* f) {
    __nv_bfloat162* h = reinterpret_cast<__nv_bfloat162*>(&ch);
    #pragma unroll
    for (int k = 0; k < 4; k++) {
        float2 t = __bfloat1622float2(h[k]);
        f[2 * k] = t.x; f[2 * k + 1] = t.y;
    }
}
__device__ __forceinline__ uint16_t pk2(float f0, float f1) {
    uint16_t r;
    asm("cvt.rn.satfinite.e4m3x2.f32 %0, %2, %1;" : "=h"(r) : "f"(f0), "f"(f1));
    return r;
}
__device__ __forceinline__ uint32_t pk4(float f0, float f1, float f2, float f3) {
    return (uint32_t)pk2(f0, f1) | ((uint32_t)pk2(f2, f3) << 16);
}

// ---------------- cvt (fp32 -> e4m3 inputs) + init : front-batched loads ----------------
__global__ void cvt_kernel(const float* __restrict__ z1,
                           const float* __restrict__ z2,
                           const float* __restrict__ W) {
    const int n8 = B_DIM * D_DIM / 8;
    const int nw8 = K_DIM * D_DIM / 8;
    int idx0 = blockIdx.x * blockDim.x + threadIdx.x;
    if (idx0 < 2 * 3 * KP)  ((float*)g_c)[idx0] = 0.0f;
    if (idx0 < 2 * B_DIM)   ((float*)g_E)[idx0] = 0.0f;
    int stride = gridDim.x * blockDim.x;
    for (int i = idx0; i < n8; i += stride) {
        // batch ALL loads first (MLP 6)
        float4 a0 = reinterpret_cast<const float4*>(z1)[i * 2];
        float4 a1 = reinterpret_cast<const float4*>(z1)[i * 2 + 1];
        float4 b0 = reinterpret_cast<const float4*>(z2)[i * 2];
        float4 b1 = reinterpret_cast<const float4*>(z2)[i * 2 + 1];
        bool w = (i < nw8);
        float4 c0, c1;
        if (w) {
            c0 = reinterpret_cast<const float4*>(W)[i * 2];
            c1 = reinterpret_cast<const float4*>(W)[i * 2 + 1];
        }
        uint2 o;
        o.x = pk4(a0.x, a0.y, a0.z, a0.w);
        o.y = pk4(a1.x, a1.y, a1.z, a1.w);
        reinterpret_cast<uint2*>(g_z8[0])[i] = o;
        o.x = pk4(b0.x, b0.y, b0.z, b0.w);
        o.y = pk4(b1.x, b1.y, b1.z, b1.w);
        reinterpret_cast<uint2*>(g_z8[1])[i] = o;
        if (w) {
            o.x = pk4(c0.x, c0.y, c0.z, c0.w);
            o.y = pk4(c1.x, c1.y, c1.z, c1.w);
            reinterpret_cast<uint2*>(g_W8)[i] = o;
        }
    }
}

// ---------------- GEMM: mma.sync fp8 e4m3, 128x128 tile, 3-stage cp.async ----------------
#define STAGE_ELEMS 5120
#define LDT 40
#define NKT 16
#define DYN_SMEM 69632

__device__ __forceinline__ void cp16(void* sdst, const void* gsrc) {
    uint32_t s = (uint32_t)__cvta_generic_to_shared(sdst);
    asm volatile("cp.async.cg.shared.global [%0], [%1], 16;" :: "r"(s), "l"(gsrc));
}

#define LDSM4(R0,R1,R2,R3,ADDR) \
    asm volatile("ldmatrix.sync.aligned.m8n8.x4.shared.b16 {%0,%1,%2,%3}, [%4];" \
                 : "=r"(R0), "=r"(R1), "=r"(R2), "=r"(R3) : "r"(ADDR))

__device__ __forceinline__ void mma16832(float* c, const uint32_t* a, const uint32_t* b) {
    asm volatile(
        "mma.sync.aligned.m16n8k32.row.col.f32.e4m3.e4m3.f32 "
        "{%0,%1,%2,%3}, {%4,%5,%6,%7}, {%8,%9}, {%0,%1,%2,%3};"
        : "+f"(c[0]), "+f"(c[1]), "+f"(c[2]), "+f"(c[3])
        : "r"(a[0]), "r"(a[1]), "r"(a[2]), "r"(a[3]), "r"(b[0]), "r"(b[1]));
}

__device__ __forceinline__ void load_stage(uint16_t* As, uint16_t* Bs,
                                           const uint16_t* Ag, int n_base,
                                           int s, int kt, int tid) {
    #pragma unroll
    for (int h = 0; h < 2; h++) {
        int c = tid + h * 256;
        int r = c >> 2, c16 = c & 3;
        cp16(As + s * STAGE_ELEMS + r * LDT + c16 * 8,
             Ag + (size_t)r * D_PK + kt * 32 + c16 * 8);
    }
    #pragma unroll
    for (int h = 0; h < 2; h++) {
        int c = tid + h * 256;
        int r = c >> 2, c16 = c & 3;
        int gn = n_base + r; if (gn >= K_DIM) gn = K_DIM - 1;
        cp16(Bs + s * STAGE_ELEMS + r * LDT + c16 * 8,
             g_W8 + (size_t)gn * D_PK + kt * 32 + c16 * 8);
    }
    asm volatile("cp.async.commit_group;");
}

__global__ void __launch_bounds__(256, 2) gemm_kernel() {
    extern __shared__ char smem_raw[];
    uint16_t* As = reinterpret_cast<uint16_t*>(smem_raw);
    uint16_t* Bs = As + 3 * STAGE_ELEMS;
    float* epi = reinterpret_cast<float*>(smem_raw);

    const int tid = threadIdx.x;
    const int bn = blockIdx.x, bm = blockIdx.y, mat = blockIdx.z;
    const uint16_t* Ag = g_z8[mat] + (size_t)bm * 128 * D_PK;
    const int n_base = bn * 128;

    load_stage(As, Bs, Ag, n_base, 0, 0, tid);
    load_stage(As, Bs, Ag, n_base, 1, 1, tid);

    float acc[2][8][4];
    #pragma unroll
    for (int a = 0; a < 2; a++)
        #pragma unroll
        for (int b = 0; b < 8; b++)
            #pragma unroll
            for (int c = 0; c < 4; c++) acc[a][b][c] = 0.0f;

    const int lane = tid & 31, wid = tid >> 5;
    const int wm = wid & 3, wn = wid >> 2;

    for (int kt = 0; kt < NKT; kt++) {
        if (kt == NKT - 1) asm volatile("cp.async.wait_group 0;");
        else               asm volatile("cp.async.wait_group 1;");
        __syncthreads();
        if (kt + 2 < NKT) load_stage(As, Bs, Ag, n_base, (kt + 2) % 3, kt + 2, tid);
        const int cur = kt % 3;
        uint32_t a_base = (uint32_t)__cvta_generic_to_shared(As + cur * STAGE_ELEMS);
        uint32_t b_base = (uint32_t)__cvta_generic_to_shared(Bs + cur * STAGE_ELEMS);
        #pragma unroll
        for (int ks = 0; ks < 2; ks++) {
            uint32_t af[2][4];
            #pragma unroll
            for (int mt = 0; mt < 2; mt++) {
                int row = wm * 32 + mt * 16 + (lane & 15);
                int col = ks * 16 + (lane >> 4) * 8;
                uint32_t ad = a_base + (uint32_t)(row * LDT + col) * 2;
                LDSM4(af[mt][0], af[mt][1], af[mt][2], af[mt][3], ad);
            }
            uint32_t bfr[8][2];
            #pragma unroll
            for (int np = 0; np < 4; np++) {
                int mi = lane >> 3;
                int nr = wn * 64 + np * 16 + (mi >> 1) * 8 + (lane & 7);
                int kc = ks * 16 + (mi & 1) * 8;
                uint32_t ad = b_base + (uint32_t)(nr * LDT + kc) * 2;
                uint32_t r0, r1, r2, r3;
                LDSM4(r0, r1, r2, r3, ad);
                bfr[np * 2][0] = r0; bfr[np * 2][1] = r1;
                bfr[np * 2 + 1][0] = r2; bfr[np * 2 + 1][1] = r3;
            }
            #pragma unroll
            for (int mt = 0; mt < 2; mt++)
                #pragma unroll
                for (int nt = 0; nt < 8; nt++)
                    mma16832(acc[mt][nt], af[mt], bfr[nt]);
        }
    }
    __syncthreads();

    // ---- epilogue: stage fp32 into smem [128][EPIT] ----
    #pragma unroll
    for (int mt = 0; mt < 2; mt++) {
        #pragma unroll
        for (int nt = 0; nt < 8; nt++) {
            int r = wm * 32 + mt * 16 + (lane >> 2);
            int cb = wn * 64 + nt * 8 + 2 * (lane & 3);
            epi[r * EPIT + cb]           = acc[mt][nt][0];
            epi[r * EPIT + cb + 1]       = acc[mt][nt][1];
            epi[(r + 8) * EPIT + cb]     = acc[mt][nt][2];
            epi[(r + 8) * EPIT + cb + 1] = acc[mt][nt][3];
        }
    }
    __syncthreads();

    int nvalid = K_DIM - n_base; if (nvalid > 128) nvalid = 128;   // 128 or 56

    // full-warp epilogue: lane handles 4 columns; ONE exp per element:
    //   e = exp(s/T);  E += e;  M = e*e = exp(s/eps)
    {
        int c4 = lane * 4;
        int g0 = n_base + c4;
        bool act = (c4 < nvalid);
        float colacc[4] = {0.f, 0.f, 0.f, 0.f};
        for (int r = wid * 16; r < wid * 16 + 16; r++) {
            int gi = bm * 128 + r;
            float esum = 0.0f;
            if (act) {
                float4 f = *reinterpret_cast<float4*>(&epi[r * EPIT + c4]);
                __nv_bfloat162 b0 = __floats2bfloat162_rn(f.x, f.y);
                __nv_bfloat162 b1 = __floats2bfloat162_rn(f.z, f.w);
                uint2 os;
                os.x = *reinterpret_cast<uint32_t*>(&b0);
                os.y = *reinterpret_cast<uint32_t*>(&b1);
                *reinterpret_cast<uint2*>(g_scores[mat] + (size_t)gi * K_DIM + g0) = os;
                float e0 = __expf(f.x * ITMP), e1 = __expf(f.y * ITMP);
                float e2 = __expf(f.z * ITMP), e3 = __expf(f.w * ITMP);
                esum = (e0 + e1) + (e2 + e3);
                float m0 = e0 * e0, m1 = e1 * e1, m2 = e2 * e2, m3 = e3 * e3;
                colacc[0] += m0; colacc[1] += m1; colacc[2] += m2; colacc[3] += m3;
                __half2 h0 = __floats2half2_rn(m0, m1);
                __half2 h1 = __floats2half2_rn(m2, m3);
                uint2 om;
                om.x = *reinterpret_cast<uint32_t*>(&h0);
                om.y = *reinterpret_cast<uint32_t*>(&h1);
                *reinterpret_cast<uint2*>(g_M[mat] + (size_t)gi * K_DIM + g0) = om;
            }
            esum = warp_red(esum);
            if (lane == 0) atomicAdd(&g_E[mat][gi], esum);
        }
        if (act) {
            #pragma unroll
            for (int k = 0; k < 4; k++)
                atomicAdd(&g_c[mat][0][g0 + k], colacc[k]);
        }
    }
}

// ---------------- fused sinkhorn iteration (R12 body): 16 rows/block, grid (256,2) ----------------
__global__ void __launch_bounds__(256) fused_pass(int iter) {
    const int mat = blockIdx.y;
    const int r0 = blockIdx.x * 16;
    __shared__ float sv[KP];
    __shared__ float sp[16];
    {
        const float4* c4 = reinterpret_cast<const float4*>(g_c[mat][iter]);
        for (int j4 = threadIdx.x; j4 < KP / 4; j4 += 256) {
            float4 c = c4[j4];
            *reinterpret_cast<float4*>(&sv[j4 * 4]) =
                make_float4(frcp(c.x), frcp(c.y), frcp(c.z), frcp(c.w));
        }
    }
    __syncthreads();
    const int wid = threadIdx.x >> 5, lane = threadIdx.x & 31;

    // phase A: row sums (warp handles 2 rows), 12-load front batch
    #pragma unroll
    for (int rr = wid * 2; rr < wid * 2 + 2; rr++) {
        int i = r0 + rr;
        const uint4* mrow = reinterpret_cast<const uint4*>(g_M[mat] + (size_t)i * K_DIM);
        uint4 buf[12];
        #pragma unroll
        for (int t = 0; t < 12; t++) {
            int idx = lane + t * 32;
            if (idx < KC8) buf[t] = mrow[idx];
        }
        float acc = 0.0f;
        #pragma unroll
        for (int t = 0; t < 12; t++) {
            int idx = lane + t * 32;
            if (idx < KC8) {
                float m[8]; unpack8h(buf[t], m);
                float4 v0 = *reinterpret_cast<const float4*>(&sv[idx * 8]);
                float4 v1 = *reinterpret_cast<const float4*>(&sv[idx * 8 + 4]);
                acc += m[0] * v0.x + m[1] * v0.y + m[2] * v0.z + m[3] * v0.w
                     + m[4] * v1.x + m[5] * v1.y + m[6] * v1.z + m[7] * v1.w;
            }
        }
        acc = warp_red(acc);
        if (lane == 0) {
            float p = acc * (1.0f / (float)K_DIM);
            sp[rr] = frcp(p) * (1.0f / (float)B_DIM);   // u_i
        }
    }
    __syncthreads();

    // phase B: column partials over same 16 rows (L1/L2-hot)
    float* cn = g_c[mat][iter + 1];
    for (int c8 = threadIdx.x; c8 < KC8; c8 += 256) {
        float a[8];
        #pragma unroll
        for (int k = 0; k < 8; k++) a[k] = 0.0f;
        #pragma unroll 4
        for (int r = 0; r < 16; r++) {
            uint4 ch = *(reinterpret_cast<const uint4*>(g_M[mat] + (size_t)(r0 + r) * K_DIM) + c8);
            float m[8]; unpack8h(ch, m);
            float u = sp[r];
            #pragma unroll
            for (int k = 0; k < 8; k++) a[k] += m[k] * u;
        }
        #pragma unroll
        for (int k = 0; k < 8; k++)
            atomicAdd(&cn[c8 * 8 + k], a[k]);
    }
}

// ---------------- iter-2 row pass + cross terms: 6+6 load batches, grid (256,2) ----------------
__global__ void __launch_bounds__(256) rowcross_kernel() {
    const int m = blockIdx.y, o = 1 - m;
    const int r0 = blockIdx.x * 16;
    __shared__ float sv[KP];
    {
        const float4* c4 = reinterpret_cast<const float4*>(g_c[m][2]);
        for (int j4 = threadIdx.x; j4 < KP / 4; j4 += 256) {
            float4 c = c4[j4];
            *reinterpret_cast<float4*>(&sv[j4 * 4]) =
                make_float4(frcp(c.x), frcp(c.y), frcp(c.z), frcp(c.w));
        }
    }
    __syncthreads();
    const int wid = threadIdx.x >> 5, lane = threadIdx.x & 31;
    for (int rr = wid; rr < 16; rr += 8) {
        int i = r0 + rr;
        const uint4* mrow = reinterpret_cast<const uint4*>(g_M[m] + (size_t)i * K_DIM);
        const uint4* srow = reinterpret_cast<const uint4*>(g_scores[o] + (size_t)i * K_DIM);
        float ap = 0.0f, at = 0.0f;
        #pragma unroll
        for (int t0 = 0; t0 < 12; t0 += 6) {
            uint4 mb[6], sb[6];
            #pragma unroll
            for (int t = 0; t < 6; t++) {
                int idx = lane + (t0 + t) * 32;
                if (idx < KC8) { mb[t] = mrow[idx]; sb[t] = srow[idx]; }
            }
            #pragma unroll
            for (int t = 0; t < 6; t++) {
                int idx = lane + (t0 + t) * 32;
                if (idx < KC8) {
                    float mm[8], x[8];
                    unpack8h(mb[t], mm); unpack8b(sb[t], x);
                    float4 v0 = *reinterpret_cast<const float4*>(&sv[idx * 8]);
                    float4 v1 = *reinterpret_cast<const float4*>(&sv[idx * 8 + 4]);
                    float vv[8] = {v0.x, v0.y, v0.z, v0.w, v1.x, v1.y, v1.z, v1.w};
                    #pragma unroll
                    for (int k = 0; k < 8; k++) {
                        float e = mm[k] * vv[k];
                        ap += e;
                        at += e * x[k];
                    }
                }
            }
        }
        ap = warp_red(ap); at = warp_red(at);
        if (lane == 0) {
            g_p[m][2][i] = ap * (1.0f / (float)K_DIM);
            g_t[m][i]    = at * (1.0f / (float)K_DIM);
        }
    }
}

// ---------------- finalize ----------------
__global__ void finalize_kernel(float* out) {
    float a = 0.0f, l = 0.0f;
    for (int i = threadIdx.x; i < B_DIM; i += blockDim.x) {
        a += g_t[0][i] / ((float)B_DIM * g_p[0][2][i])
           + g_t[1][i] / ((float)B_DIM * g_p[1][2][i]);
        l += __logf(g_E[0][i]) + __logf(g_E[1][i]);
    }
    a = warp_red(a); l = warp_red(l);
    __shared__ float sa[8], sl[8];
    int lane = threadIdx.x & 31, wid = threadIdx.x >> 5;
    if (lane == 0) { sa[wid] = a; sl[wid] = l; }
    __syncthreads();
    if (threadIdx.x == 0) {
        float ta = 0.f, tl = 0.f;
        for (int w = 0; w < 8; w++) { ta += sa[w]; tl += sl[w]; }
        float loss = -0.5f * (ta / ((float)B_DIM * TEMP)
                              - tl / ((float)B_DIM * (float)B_DIM));
        out[0] = loss;
    }
}

// ---------------- launch (single stream) ----------------
extern "C" void kernel_launch(void* const* d_in, const int* in_sizes, int n_in,
                              void* d_out, int out_size) {
    const float* z1 = (const float*)d_in[0];
    const float* z2 = (const float*)d_in[1];
    const float* W  = (const float*)d_in[2];
    float* out = (float*)d_out;

    cudaFuncSetAttribute(gemm_kernel, cudaFuncAttributeMaxDynamicSharedMemorySize, DYN_SMEM);

    cvt_kernel<<<2048, 256>>>(z1, z2, W);

    dim3 ggrid(24, 32, 2);
    gemm_kernel<<<ggrid, 256, DYN_SMEM>>>();

    fused_pass<<<dim3(256, 2), 256>>>(0);     // p0 + c1
    fused_pass<<<dim3(256, 2), 256>>>(1);     // p1 + c2
    rowcross_kernel<<<dim3(256, 2), 256>>>(); // p2 + t
    finalize_kernel<<<1, 256>>>(out);
}

// round 15
// speedup vs baseline: 1.1575x; 1.1323x over previous
#include <cuda_runtime.h>
#include <cuda_bf16.h>
#include <cuda_fp16.h>
#include <cstdint>

#define B_DIM 4096
#define D_DIM 1024
#define D_PK  512          // packed fp8 pairs per row (uint16 units)
#define K_DIM 3000
#define KC8   375          // K_DIM / 8 : 16B chunks per 16-bit row
#define KP    3008
#define IEPS  20.0f
#define ITMP  10.0f
#define TEMP  0.1f
#define EPIT  132          // epilogue smem pitch (floats)

// ---------------- scratch ----------------
__device__ __align__(256) __nv_bfloat16  g_scores[2][(size_t)B_DIM * K_DIM]; // 49.2 MB (s)
__device__ __align__(256) __half         g_M[2][(size_t)B_DIM * K_DIM];      // 49.2 MB (exp(s/eps))
__device__ __align__(256) uint16_t       g_z8[2][(size_t)B_DIM * D_PK];      //  8.4 MB
__device__ __align__(256) uint16_t       g_W8[(size_t)K_DIM * D_PK];         //  3.1 MB
__device__ __align__(256) float          g_c [2][3][KP];
__device__ __align__(256) float          g_p [2][3][B_DIM];
__device__ __align__(256) float          g_E [2][B_DIM];
__device__ __align__(256) float          g_t [2][B_DIM];

// ---------------- helpers ----------------
__device__ __forceinline__ float warp_red(float v) {
    #pragma unroll
    for (int o = 16; o; o >>= 1) v += __shfl_xor_sync(0xffffffffu, v, o);
    return v;
}
__device__ __forceinline__ float frcp(float x) {
    float r; asm("rcp.approx.f32 %0, %1;" : "=f"(r) : "f"(x)); return r;
}
__device__ __forceinline__ void unpack8h(uint4 ch, float* f) {
    __half2* h = reinterpret_cast<__half2*>(&ch);
    #pragma unroll
    for (int k = 0; k < 4; k++) {
        float2 t = __half22float2(h[k]);
        f[2 * k] = t.x; f[2 * k + 1] = t.y;
    }
}
__device__ __forceinline__ void unpack8b(uint4 ch, float* f) {
    __nv_bfloat162* h = reinterpret_cast<__nv_bfloat162*>(&ch);
    #pragma unroll
    for (int k = 0; k < 4; k++) {
        float2 t = __bfloat1622float2(h[k]);
        f[2 * k] = t.x; f[2 * k + 1] = t.y;
    }
}
__device__ __forceinline__ uint16_t pk2(float f0, float f1) {
    uint16_t r;
    asm("cvt.rn.satfinite.e4m3x2.f32 %0, %2, %1;" : "=h"(r) : "f"(f0), "f"(f1));
    return r;
}
__device__ __forceinline__ uint32_t pk4(float f0, float f1, float f2, float f3) {
    return (uint32_t)pk2(f0, f1) | ((uint32_t)pk2(f2, f3) << 16);
}

// ---------------- cvt (fp32 -> e4m3 inputs) + init : front-batched loads ----------------
__global__ void cvt_kernel(const float* __restrict__ z1,
                           const float* __restrict__ z2,
                           const float* __restrict__ W) {
    const int n8 = B_DIM * D_DIM / 8;
    const int nw8 = K_DIM * D_DIM / 8;
    int idx0 = blockIdx.x * blockDim.x + threadIdx.x;
    if (idx0 < 2 * 3 * KP)  ((float*)g_c)[idx0] = 0.0f;
    if (idx0 < 2 * B_DIM)   ((float*)g_E)[idx0] = 0.0f;
    int stride = gridDim.x * blockDim.x;
    for (int i = idx0; i < n8; i += stride) {
        float4 a0 = reinterpret_cast<const float4*>(z1)[i * 2];
        float4 a1 = reinterpret_cast<const float4*>(z1)[i * 2 + 1];
        float4 b0 = reinterpret_cast<const float4*>(z2)[i * 2];
        float4 b1 = reinterpret_cast<const float4*>(z2)[i * 2 + 1];
        bool w = (i < nw8);
        float4 c0, c1;
        if (w) {
            c0 = reinterpret_cast<const float4*>(W)[i * 2];
            c1 = reinterpret_cast<const float4*>(W)[i * 2 + 1];
        }
        uint2 o;
        o.x = pk4(a0.x, a0.y, a0.z, a0.w);
        o.y = pk4(a1.x, a1.y, a1.z, a1.w);
        reinterpret_cast<uint2*>(g_z8[0])[i] = o;
        o.x = pk4(b0.x, b0.y, b0.z, b0.w);
        o.y = pk4(b1.x, b1.y, b1.z, b1.w);
        reinterpret_cast<uint2*>(g_z8[1])[i] = o;
        if (w) {
            o.x = pk4(c0.x, c0.y, c0.z, c0.w);
            o.y = pk4(c1.x, c1.y, c1.z, c1.w);
            reinterpret_cast<uint2*>(g_W8)[i] = o;
        }
    }
}

// ---------------- GEMM: mma.sync fp8 e4m3, 128x128 tile, 3-stage cp.async ----------------
#define STAGE_ELEMS 5120
#define LDT 40
#define NKT 16
#define DYN_SMEM 69632

__device__ __forceinline__ void cp16(void* sdst, const void* gsrc) {
    uint32_t s = (uint32_t)__cvta_generic_to_shared(sdst);
    asm volatile("cp.async.cg.shared.global [%0], [%1], 16;" :: "r"(s), "l"(gsrc));
}

#define LDSM4(R0,R1,R2,R3,ADDR) \
    asm volatile("ldmatrix.sync.aligned.m8n8.x4.shared.b16 {%0,%1,%2,%3}, [%4];" \
                 : "=r"(R0), "=r"(R1), "=r"(R2), "=r"(R3) : "r"(ADDR))

__device__ __forceinline__ void mma16832(float* c, const uint32_t* a, const uint32_t* b) {
    asm volatile(
        "mma.sync.aligned.m16n8k32.row.col.f32.e4m3.e4m3.f32 "
        "{%0,%1,%2,%3}, {%4,%5,%6,%7}, {%8,%9}, {%0,%1,%2,%3};"
        : "+f"(c[0]), "+f"(c[1]), "+f"(c[2]), "+f"(c[3])
        : "r"(a[0]), "r"(a[1]), "r"(a[2]), "r"(a[3]), "r"(b[0]), "r"(b[1]));
}

__device__ __forceinline__ void load_stage(uint16_t* As, uint16_t* Bs,
                                           const uint16_t* Ag, int n_base,
                                           int s, int kt, int tid) {
    #pragma unroll
    for (int h = 0; h < 2; h++) {
        int c = tid + h * 256;
        int r = c >> 2, c16 = c & 3;
        cp16(As + s * STAGE_ELEMS + r * LDT + c16 * 8,
             Ag + (size_t)r * D_PK + kt * 32 + c16 * 8);
    }
    #pragma unroll
    for (int h = 0; h < 2; h++) {
        int c = tid + h * 256;
        int r = c >> 2, c16 = c & 3;
        int gn = n_base + r; if (gn >= K_DIM) gn = K_DIM - 1;
        cp16(Bs + s * STAGE_ELEMS + r * LDT + c16 * 8,
             g_W8 + (size_t)gn * D_PK + kt * 32 + c16 * 8);
    }
    asm volatile("cp.async.commit_group;");
}

__global__ void __launch_bounds__(256, 2) gemm_kernel() {
    extern __shared__ char smem_raw[];
    uint16_t* As = reinterpret_cast<uint16_t*>(smem_raw);
    uint16_t* Bs = As + 3 * STAGE_ELEMS;
    float* epi = reinterpret_cast<float*>(smem_raw);

    const int tid = threadIdx.x;
    const int bn = blockIdx.x, bm = blockIdx.y, mat = blockIdx.z;
    const uint16_t* Ag = g_z8[mat] + (size_t)bm * 128 * D_PK;
    const int n_base = bn * 128;

    load_stage(As, Bs, Ag, n_base, 0, 0, tid);
    load_stage(As, Bs, Ag, n_base, 1, 1, tid);

    float acc[2][8][4];
    #pragma unroll
    for (int a = 0; a < 2; a++)
        #pragma unroll
        for (int b = 0; b < 8; b++)
            #pragma unroll
            for (int c = 0; c < 4; c++) acc[a][b][c] = 0.0f;

    const int lane = tid & 31, wid = tid >> 5;
    const int wm = wid & 3, wn = wid >> 2;

    for (int kt = 0; kt < NKT; kt++) {
        if (kt == NKT - 1) asm volatile("cp.async.wait_group 0;");
        else               asm volatile("cp.async.wait_group 1;");
        __syncthreads();
        if (kt + 2 < NKT) load_stage(As, Bs, Ag, n_base, (kt + 2) % 3, kt + 2, tid);
        const int cur = kt % 3;
        uint32_t a_base = (uint32_t)__cvta_generic_to_shared(As + cur * STAGE_ELEMS);
        uint32_t b_base = (uint32_t)__cvta_generic_to_shared(Bs + cur * STAGE_ELEMS);
        #pragma unroll
        for (int ks = 0; ks < 2; ks++) {
            uint32_t af[2][4];
            #pragma unroll
            for (int mt = 0; mt < 2; mt++) {
                int row = wm * 32 + mt * 16 + (lane & 15);
                int col = ks * 16 + (lane >> 4) * 8;
                uint32_t ad = a_base + (uint32_t)(row * LDT + col) * 2;
                LDSM4(af[mt][0], af[mt][1], af[mt][2], af[mt][3], ad);
            }
            uint32_t bfr[8][2];
            #pragma unroll
            for (int np = 0; np < 4; np++) {
                int mi = lane >> 3;
                int nr = wn * 64 + np * 16 + (mi >> 1) * 8 + (lane & 7);
                int kc = ks * 16 + (mi & 1) * 8;
                uint32_t ad = b_base + (uint32_t)(nr * LDT + kc) * 2;
                uint32_t r0, r1, r2, r3;
                LDSM4(r0, r1, r2, r3, ad);
                bfr[np * 2][0] = r0; bfr[np * 2][1] = r1;
                bfr[np * 2 + 1][0] = r2; bfr[np * 2 + 1][1] = r3;
            }
            #pragma unroll
            for (int mt = 0; mt < 2; mt++)
                #pragma unroll
                for (int nt = 0; nt < 8; nt++)
                    mma16832(acc[mt][nt], af[mt], bfr[nt]);
        }
    }
    __syncthreads();

    // ---- epilogue: stage fp32 into smem [128][EPIT] ----
    #pragma unroll
    for (int mt = 0; mt < 2; mt++) {
        #pragma unroll
        for (int nt = 0; nt < 8; nt++) {
            int r = wm * 32 + mt * 16 + (lane >> 2);
            int cb = wn * 64 + nt * 8 + 2 * (lane & 3);
            epi[r * EPIT + cb]           = acc[mt][nt][0];
            epi[r * EPIT + cb + 1]       = acc[mt][nt][1];
            epi[(r + 8) * EPIT + cb]     = acc[mt][nt][2];
            epi[(r + 8) * EPIT + cb + 1] = acc[mt][nt][3];
        }
    }
    __syncthreads();

    int nvalid = K_DIM - n_base; if (nvalid > 128) nvalid = 128;   // 128 or 56

    // full-warp epilogue: lane handles 4 columns; ONE exp per element:
    //   e = exp(s/T);  E += e;  M = e*e = exp(s/eps)
    {
        int c4 = lane * 4;
        int g0 = n_base + c4;
        bool act = (c4 < nvalid);
        float colacc[4] = {0.f, 0.f, 0.f, 0.f};
        for (int r = wid * 16; r < wid * 16 + 16; r++) {
            int gi = bm * 128 + r;
            float esum = 0.0f;
            if (act) {
                float4 f = *reinterpret_cast<float4*>(&epi[r * EPIT + c4]);
                __nv_bfloat162 b0 = __floats2bfloat162_rn(f.x, f.y);
                __nv_bfloat162 b1 = __floats2bfloat162_rn(f.z, f.w);
                uint2 os;
                os.x = *reinterpret_cast<uint32_t*>(&b0);
                os.y = *reinterpret_cast<uint32_t*>(&b1);
                *reinterpret_cast<uint2*>(g_scores[mat] + (size_t)gi * K_DIM + g0) = os;
                float e0 = __expf(f.x * ITMP), e1 = __expf(f.y * ITMP);
                float e2 = __expf(f.z * ITMP), e3 = __expf(f.w * ITMP);
                esum = (e0 + e1) + (e2 + e3);
                float m0 = e0 * e0, m1 = e1 * e1, m2 = e2 * e2, m3 = e3 * e3;
                colacc[0] += m0; colacc[1] += m1; colacc[2] += m2; colacc[3] += m3;
                __half2 h0 = __floats2half2_rn(m0, m1);
                __half2 h1 = __floats2half2_rn(m2, m3);
                uint2 om;
                om.x = *reinterpret_cast<uint32_t*>(&h0);
                om.y = *reinterpret_cast<uint32_t*>(&h1);
                *reinterpret_cast<uint2*>(g_M[mat] + (size_t)gi * K_DIM + g0) = om;
            }
            esum = warp_red(esum);
            if (lane == 0) atomicAdd(&g_E[mat][gi], esum);
        }
        if (act) {
            #pragma unroll
            for (int k = 0; k < 4; k++)
                atomicAdd(&g_c[mat][0][g0 + k], colacc[k]);
        }
    }
}

// ---------------- fused sinkhorn iteration: 32 rows/block, grid (128,2) = 1 wave ----------------
__global__ void __launch_bounds__(256) fused_pass(int iter) {
    const int mat = blockIdx.y;
    const int r0 = blockIdx.x * 32;
    __shared__ float sv[KP];
    __shared__ float sp[32];
    {
        const float4* c4 = reinterpret_cast<const float4*>(g_c[mat][iter]);
        for (int j4 = threadIdx.x; j4 < KP / 4; j4 += 256) {
            float4 c = c4[j4];
            *reinterpret_cast<float4*>(&sv[j4 * 4]) =
                make_float4(frcp(c.x), frcp(c.y), frcp(c.z), frcp(c.w));
        }
    }
    __syncthreads();
    const int wid = threadIdx.x >> 5, lane = threadIdx.x & 31;

    // phase A: row sums (warp handles 4 rows), 12-load front batch per row
    #pragma unroll
    for (int rr = wid * 4; rr < wid * 4 + 4; rr++) {
        int i = r0 + rr;
        const uint4* mrow = reinterpret_cast<const uint4*>(g_M[mat] + (size_t)i * K_DIM);
        uint4 buf[12];
        #pragma unroll
        for (int t = 0; t < 12; t++) {
            int idx = lane + t * 32;
            if (idx < KC8) buf[t] = mrow[idx];
        }
        float acc = 0.0f;
        #pragma unroll
        for (int t = 0; t < 12; t++) {
            int idx = lane + t * 32;
            if (idx < KC8) {
                float m[8]; unpack8h(buf[t], m);
                float4 v0 = *reinterpret_cast<const float4*>(&sv[idx * 8]);
                float4 v1 = *reinterpret_cast<const float4*>(&sv[idx * 8 + 4]);
                acc += m[0] * v0.x + m[1] * v0.y + m[2] * v0.z + m[3] * v0.w
                     + m[4] * v1.x + m[5] * v1.y + m[6] * v1.z + m[7] * v1.w;
            }
        }
        acc = warp_red(acc);
        if (lane == 0) {
            float p = acc * (1.0f / (float)K_DIM);
            sp[rr] = frcp(p) * (1.0f / (float)B_DIM);   // u_i
        }
    }
    __syncthreads();

    // phase B: column partials over same 32 rows (L1/L2-hot)
    float* cn = g_c[mat][iter + 1];
    for (int c8 = threadIdx.x; c8 < KC8; c8 += 256) {
        float a[8];
        #pragma unroll
        for (int k = 0; k < 8; k++) a[k] = 0.0f;
        #pragma unroll 4
        for (int r = 0; r < 32; r++) {
            uint4 ch = *(reinterpret_cast<const uint4*>(g_M[mat] + (size_t)(r0 + r) * K_DIM) + c8);
            float m[8]; unpack8h(ch, m);
            float u = sp[r];
            #pragma unroll
            for (int k = 0; k < 8; k++) a[k] += m[k] * u;
        }
        #pragma unroll
        for (int k = 0; k < 8; k++)
            atomicAdd(&cn[c8 * 8 + k], a[k]);
    }
}

// ---------------- iter-2 row pass + cross terms: 32 rows/block, grid (128,2) ----------------
__global__ void __launch_bounds__(256) rowcross_kernel() {
    const int m = blockIdx.y, o = 1 - m;
    const int r0 = blockIdx.x * 32;
    __shared__ float sv[KP];
    {
        const float4* c4 = reinterpret_cast<const float4*>(g_c[m][2]);
        for (int j4 = threadIdx.x; j4 < KP / 4; j4 += 256) {
            float4 c = c4[j4];
            *reinterpret_cast<float4*>(&sv[j4 * 4]) =
                make_float4(frcp(c.x), frcp(c.y), frcp(c.z), frcp(c.w));
        }
    }
    __syncthreads();
    const int wid = threadIdx.x >> 5, lane = threadIdx.x & 31;
    #pragma unroll
    for (int rr = wid * 4; rr < wid * 4 + 4; rr++) {
        int i = r0 + rr;
        const uint4* mrow = reinterpret_cast<const uint4*>(g_M[m] + (size_t)i * K_DIM);
        const uint4* srow = reinterpret_cast<const uint4*>(g_scores[o] + (size_t)i * K_DIM);
        float ap = 0.0f, at = 0.0f;
        #pragma unroll
        for (int t0 = 0; t0 < 12; t0 += 3) {
            uint4 mb[3], sb[3];
            #pragma unroll
            for (int t = 0; t < 3; t++) {
                int idx = lane + (t0 + t) * 32;
                if (idx < KC8) { mb[t] = mrow[idx]; sb[t] = srow[idx]; }
            }
            #pragma unroll
            for (int t = 0; t < 3; t++) {
                int idx = lane + (t0 + t) * 32;
                if (idx < KC8) {
                    float mm[8], x[8];
                    unpack8h(mb[t], mm); unpack8b(sb[t], x);
                    float4 v0 = *reinterpret_cast<const float4*>(&sv[idx * 8]);
                    float4 v1 = *reinterpret_cast<const float4*>(&sv[idx * 8 + 4]);
                    float vv[8] = {v0.x, v0.y, v0.z, v0.w, v1.x, v1.y, v1.z, v1.w};
                    #pragma unroll
                    for (int k = 0; k < 8; k++) {
                        float e = mm[k] * vv[k];
                        ap += e;
                        at += e * x[k];
                    }
                }
            }
        }
        ap = warp_red(ap); at = warp_red(at);
        if (lane == 0) {
            g_p[m][2][i] = ap * (1.0f / (float)K_DIM);
            g_t[m][i]    = at * (1.0f / (float)K_DIM);
        }
    }
}

// ---------------- finalize ----------------
__global__ void finalize_kernel(float* out) {
    float a = 0.0f, l = 0.0f;
    for (int i = threadIdx.x; i < B_DIM; i += blockDim.x) {
        a += g_t[0][i] / ((float)B_DIM * g_p[0][2][i])
           + g_t[1][i] / ((float)B_DIM * g_p[1][2][i]);
        l += __logf(g_E[0][i]) + __logf(g_E[1][i]);
    }
    a = warp_red(a); l = warp_red(l);
    __shared__ float sa[8], sl[8];
    int lane = threadIdx.x & 31, wid = threadIdx.x >> 5;
    if (lane == 0) { sa[wid] = a; sl[wid] = l; }
    __syncthreads();
    if (threadIdx.x == 0) {
        float ta = 0.f, tl = 0.f;
        for (int w = 0; w < 8; w++) { ta += sa[w]; tl += sl[w]; }
        float loss = -0.5f * (ta / ((float)B_DIM * TEMP)
                              - tl / ((float)B_DIM * (float)B_DIM));
        out[0] = loss;
    }
}

// ---------------- launch (single stream) ----------------
extern "C" void kernel_launch(void* const* d_in, const int* in_sizes, int n_in,
                              void* d_out, int out_size) {
    const float* z1 = (const float*)d_in[0];
    const float* z2 = (const float*)d_in[1];
    const float* W  = (const float*)d_in[2];
    float* out = (float*)d_out;

    cudaFuncSetAttribute(gemm_kernel, cudaFuncAttributeMaxDynamicSharedMemorySize, DYN_SMEM);

    cvt_kernel<<<2048, 256>>>(z1, z2, W);

    dim3 ggrid(24, 32, 2);
    gemm_kernel<<<ggrid, 256, DYN_SMEM>>>();

    fused_pass<<<dim3(128, 2), 256>>>(0);     // p0 + c1
    fused_pass<<<dim3(128, 2), 256>>>(1);     // p1 + c2
    rowcross_kernel<<<dim3(128, 2), 256>>>(); // p2 + t
    finalize_kernel<<<1, 256>>>(out);
}

// round 16
// speedup vs baseline: 1.1759x; 1.0158x over previous
#include <cuda_runtime.h>
#include <cuda_bf16.h>
#include <cuda_fp16.h>
#include <cstdint>

#define B_DIM 4096
#define D_DIM 1024
#define D_PK  512          // packed fp8 pairs per row (uint16 units)
#define K_DIM 3000
#define KP    3008         // padded pitch (elements) for scores + M8
#define KC16  188          // KP/16 : 16B fp8 chunks per row
#define IEPS  20.0f
#define ITMP  10.0f
#define TEMP  0.1f
#define EPIT  132          // epilogue smem pitch (floats)

// ---------------- scratch ----------------
__device__ __align__(256) __nv_bfloat16  g_scores[2][(size_t)B_DIM * KP];  // 49.3 MB (s, padded)
__device__ __align__(256) uint8_t        g_M8[2][(size_t)B_DIM * KP];      // 24.6 MB (exp(s/eps) e4m3)
__device__ __align__(256) uint16_t       g_z8[2][(size_t)B_DIM * D_PK];    //  8.4 MB
__device__ __align__(256) uint16_t       g_W8[(size_t)K_DIM * D_PK];       //  3.1 MB
__device__ __align__(256) float          g_c [2][3][KP];
__device__ __align__(256) float          g_p [2][3][B_DIM];
__device__ __align__(256) float          g_E [2][B_DIM];
__device__ __align__(256) float          g_t [2][B_DIM];

// ---------------- helpers ----------------
__device__ __forceinline__ float warp_red(float v) {
    #pragma unroll
    for (int o = 16; o; o >>= 1) v += __shfl_xor_sync(0xffffffffu, v, o);
    return v;
}
__device__ __forceinline__ float frcp(float x) {
    float r; asm("rcp.approx.f32 %0, %1;" : "=f"(r) : "f"(x)); return r;
}
__device__ __forceinline__ void unpack8b(uint4 ch, float* f) {
    __nv_bfloat162* h = reinterpret_cast<__nv_bfloat162*>(&ch);
    #pragma unroll
    for (int k = 0; k < 4; k++) {
        float2 t = __bfloat1622float2(h[k]);
        f[2 * k] = t.x; f[2 * k + 1] = t.y;
    }
}
// decode 16 e4m3 bytes -> 16 floats (byte i -> f[i])
__device__ __forceinline__ void unpack16f8(uint4 ch, float* f) {
    uint16_t b[8];
    *reinterpret_cast<uint4*>(b) = ch;
    #pragma unroll
    for (int k = 0; k < 8; k++) {
        uint32_t h2;
        asm("cvt.rn.f16x2.e4m3x2 %0, %1;" : "=r"(h2) : "h"(b[k]));
        __half2 hh = *reinterpret_cast<__half2*>(&h2);
        float2 t = __half22float2(hh);
        f[2 * k] = t.x; f[2 * k + 1] = t.y;
    }
}
__device__ __forceinline__ uint16_t pk2(float f0, float f1) {
    uint16_t r;
    asm("cvt.rn.satfinite.e4m3x2.f32 %0, %2, %1;" : "=h"(r) : "f"(f0), "f"(f1));
    return r;
}
__device__ __forceinline__ uint32_t pk4(float f0, float f1, float f2, float f3) {
    return (uint32_t)pk2(f0, f1) | ((uint32_t)pk2(f2, f3) << 16);
}

// ---------------- cvt (fp32 -> e4m3 inputs) + init ----------------
__global__ void cvt_kernel(const float* __restrict__ z1,
                           const float* __restrict__ z2,
                           const float* __restrict__ W) {
    const int n8 = B_DIM * D_DIM / 8;
    const int nw8 = K_DIM * D_DIM / 8;
    int idx0 = blockIdx.x * blockDim.x + threadIdx.x;
    if (idx0 < 2 * 3 * KP) {
        int j = idx0 % KP;
        ((float*)g_c)[idx0] = (j >= K_DIM) ? 1.0f : 0.0f;   // pad c=1 avoids rcp(0)
    }
    if (idx0 < 2 * B_DIM)   ((float*)g_E)[idx0] = 0.0f;
    int stride = gridDim.x * blockDim.x;
    for (int i = idx0; i < n8; i += stride) {
        float4 a0 = reinterpret_cast<const float4*>(z1)[i * 2];
        float4 a1 = reinterpret_cast<const float4*>(z1)[i * 2 + 1];
        float4 b0 = reinterpret_cast<const float4*>(z2)[i * 2];
        float4 b1 = reinterpret_cast<const float4*>(z2)[i * 2 + 1];
        bool w = (i < nw8);
        float4 c0, c1;
        if (w) {
            c0 = reinterpret_cast<const float4*>(W)[i * 2];
            c1 = reinterpret_cast<const float4*>(W)[i * 2 + 1];
        }
        uint2 o;
        o.x = pk4(a0.x, a0.y, a0.z, a0.w);
        o.y = pk4(a1.x, a1.y, a1.z, a1.w);
        reinterpret_cast<uint2*>(g_z8[0])[i] = o;
        o.x = pk4(b0.x, b0.y, b0.z, b0.w);
        o.y = pk4(b1.x, b1.y, b1.z, b1.w);
        reinterpret_cast<uint2*>(g_z8[1])[i] = o;
        if (w) {
            o.x = pk4(c0.x, c0.y, c0.z, c0.w);
            o.y = pk4(c1.x, c1.y, c1.z, c1.w);
            reinterpret_cast<uint2*>(g_W8)[i] = o;
        }
    }
}

// ---------------- GEMM: mma.sync fp8 e4m3, 128x128 tile, 3-stage cp.async ----------------
#define STAGE_ELEMS 5120
#define LDT 40
#define NKT 16
#define DYN_SMEM 69632

__device__ __forceinline__ void cp16(void* sdst, const void* gsrc) {
    uint32_t s = (uint32_t)__cvta_generic_to_shared(sdst);
    asm volatile("cp.async.cg.shared.global [%0], [%1], 16;" :: "r"(s), "l"(gsrc));
}

#define LDSM4(R0,R1,R2,R3,ADDR) \
    asm volatile("ldmatrix.sync.aligned.m8n8.x4.shared.b16 {%0,%1,%2,%3}, [%4];" \
                 : "=r"(R0), "=r"(R1), "=r"(R2), "=r"(R3) : "r"(ADDR))

__device__ __forceinline__ void mma16832(float* c, const uint32_t* a, const uint32_t* b) {
    asm volatile(
        "mma.sync.aligned.m16n8k32.row.col.f32.e4m3.e4m3.f32 "
        "{%0,%1,%2,%3}, {%4,%5,%6,%7}, {%8,%9}, {%0,%1,%2,%3};"
        : "+f"(c[0]), "+f"(c[1]), "+f"(c[2]), "+f"(c[3])
        : "r"(a[0]), "r"(a[1]), "r"(a[2]), "r"(a[3]), "r"(b[0]), "r"(b[1]));
}

__device__ __forceinline__ void load_stage(uint16_t* As, uint16_t* Bs,
                                           const uint16_t* Ag, int n_base,
                                           int s, int kt, int tid) {
    #pragma unroll
    for (int h = 0; h < 2; h++) {
        int c = tid + h * 256;
        int r = c >> 2, c16 = c & 3;
        cp16(As + s * STAGE_ELEMS + r * LDT + c16 * 8,
             Ag + (size_t)r * D_PK + kt * 32 + c16 * 8);
    }
    #pragma unroll
    for (int h = 0; h < 2; h++) {
        int c = tid + h * 256;
        int r = c >> 2, c16 = c & 3;
        int gn = n_base + r; if (gn >= K_DIM) gn = K_DIM - 1;
        cp16(Bs + s * STAGE_ELEMS + r * LDT + c16 * 8,
             g_W8 + (size_t)gn * D_PK + kt * 32 + c16 * 8);
    }
    asm volatile("cp.async.commit_group;");
}

__global__ void __launch_bounds__(256, 2) gemm_kernel() {
    extern __shared__ char smem_raw[];
    uint16_t* As = reinterpret_cast<uint16_t*>(smem_raw);
    uint16_t* Bs = As + 3 * STAGE_ELEMS;
    float* epi = reinterpret_cast<float*>(smem_raw);

    const int tid = threadIdx.x;
    const int bn = blockIdx.x, bm = blockIdx.y, mat = blockIdx.z;
    const uint16_t* Ag = g_z8[mat] + (size_t)bm * 128 * D_PK;
    const int n_base = bn * 128;

    load_stage(As, Bs, Ag, n_base, 0, 0, tid);
    load_stage(As, Bs, Ag, n_base, 1, 1, tid);

    float acc[2][8][4];
    #pragma unroll
    for (int a = 0; a < 2; a++)
        #pragma unroll
        for (int b = 0; b < 8; b++)
            #pragma unroll
            for (int c = 0; c < 4; c++) acc[a][b][c] = 0.0f;

    const int lane = tid & 31, wid = tid >> 5;
    const int wm = wid & 3, wn = wid >> 2;

    for (int kt = 0; kt < NKT; kt++) {
        if (kt == NKT - 1) asm volatile("cp.async.wait_group 0;");
        else               asm volatile("cp.async.wait_group 1;");
        __syncthreads();
        if (kt + 2 < NKT) load_stage(As, Bs, Ag, n_base, (kt + 2) % 3, kt + 2, tid);
        const int cur = kt % 3;
        uint32_t a_base = (uint32_t)__cvta_generic_to_shared(As + cur * STAGE_ELEMS);
        uint32_t b_base = (uint32_t)__cvta_generic_to_shared(Bs + cur * STAGE_ELEMS);
        #pragma unroll
        for (int ks = 0; ks < 2; ks++) {
            uint32_t af[2][4];
            #pragma unroll
            for (int mt = 0; mt < 2; mt++) {
                int row = wm * 32 + mt * 16 + (lane & 15);
                int col = ks * 16 + (lane >> 4) * 8;
                uint32_t ad = a_base + (uint32_t)(row * LDT + col) * 2;
                LDSM4(af[mt][0], af[mt][1], af[mt][2], af[mt][3], ad);
            }
            uint32_t bfr[8][2];
            #pragma unroll
            for (int np = 0; np < 4; np++) {
                int mi = lane >> 3;
                int nr = wn * 64 + np * 16 + (mi >> 1) * 8 + (lane & 7);
                int kc = ks * 16 + (mi & 1) * 8;
                uint32_t ad = b_base + (uint32_t)(nr * LDT + kc) * 2;
                uint32_t r0, r1, r2, r3;
                LDSM4(r0, r1, r2, r3, ad);
                bfr[np * 2][0] = r0; bfr[np * 2][1] = r1;
                bfr[np * 2 + 1][0] = r2; bfr[np * 2 + 1][1] = r3;
            }
            #pragma unroll
            for (int mt = 0; mt < 2; mt++)
                #pragma unroll
                for (int nt = 0; nt < 8; nt++)
                    mma16832(acc[mt][nt], af[mt], bfr[nt]);
        }
    }
    __syncthreads();

    // ---- epilogue: stage fp32 into smem [128][EPIT] ----
    #pragma unroll
    for (int mt = 0; mt < 2; mt++) {
        #pragma unroll
        for (int nt = 0; nt < 8; nt++) {
            int r = wm * 32 + mt * 16 + (lane >> 2);
            int cb = wn * 64 + nt * 8 + 2 * (lane & 3);
            epi[r * EPIT + cb]           = acc[mt][nt][0];
            epi[r * EPIT + cb + 1]       = acc[mt][nt][1];
            epi[(r + 8) * EPIT + cb]     = acc[mt][nt][2];
            epi[(r + 8) * EPIT + cb + 1] = acc[mt][nt][3];
        }
    }
    __syncthreads();

    int nvalid = K_DIM - n_base; if (nvalid > 128) nvalid = 128;   // 128 or 56

    // full-warp epilogue: lane handles 4 columns; ONE exp per element:
    //   e = exp(s/T);  E += e;  M = e*e = exp(s/eps) -> e4m3
    {
        int c4 = lane * 4;
        int g0 = n_base + c4;
        bool act = (c4 < nvalid);
        bool pad = (!act) && (g0 >= K_DIM) && (g0 + 4 <= KP);   // zero the 8 pad cols (tail block)
        float colacc[4] = {0.f, 0.f, 0.f, 0.f};
        for (int r = wid * 16; r < wid * 16 + 16; r++) {
            int gi = bm * 128 + r;
            float esum = 0.0f;
            if (act) {
                float4 f = *reinterpret_cast<float4*>(&epi[r * EPIT + c4]);
                __nv_bfloat162 b0 = __floats2bfloat162_rn(f.x, f.y);
                __nv_bfloat162 b1 = __floats2bfloat162_rn(f.z, f.w);
                uint2 os;
                os.x = *reinterpret_cast<uint32_t*>(&b0);
                os.y = *reinterpret_cast<uint32_t*>(&b1);
                *reinterpret_cast<uint2*>(g_scores[mat] + (size_t)gi * KP + g0) = os;
                float e0 = __expf(f.x * ITMP), e1 = __expf(f.y * ITMP);
                float e2 = __expf(f.z * ITMP), e3 = __expf(f.w * ITMP);
                esum = (e0 + e1) + (e2 + e3);
                float m0 = e0 * e0, m1 = e1 * e1, m2 = e2 * e2, m3 = e3 * e3;
                colacc[0] += m0; colacc[1] += m1; colacc[2] += m2; colacc[3] += m3;
                *reinterpret_cast<uint32_t*>(g_M8[mat] + (size_t)gi * KP + g0) =
                    pk4(m0, m1, m2, m3);
            } else if (pad) {
                *reinterpret_cast<uint2*>(g_scores[mat] + (size_t)gi * KP + g0) = make_uint2(0, 0);
                *reinterpret_cast<uint32_t*>(g_M8[mat] + (size_t)gi * KP + g0) = 0u;
            }
            esum = warp_red(esum);
            if (lane == 0) atomicAdd(&g_E[mat][gi], esum);
        }
        if (act) {
            #pragma unroll
            for (int k = 0; k < 4; k++)
                atomicAdd(&g_c[mat][0][g0 + k], colacc[k]);
        }
    }
}

// ---------------- fused sinkhorn iteration: fp8 M, 32 rows/block, grid (128,2) ----------------
__global__ void __launch_bounds__(256) fused_pass(int iter) {
    const int mat = blockIdx.y;
    const int r0 = blockIdx.x * 32;
    __shared__ float sv[KP];
    __shared__ float sp[32];
    {
        const float4* c4 = reinterpret_cast<const float4*>(g_c[mat][iter]);
        for (int j4 = threadIdx.x; j4 < KP / 4; j4 += 256) {
            float4 c = c4[j4];
            *reinterpret_cast<float4*>(&sv[j4 * 4]) =
                make_float4(frcp(c.x), frcp(c.y), frcp(c.z), frcp(c.w));
        }
    }
    __syncthreads();
    const int wid = threadIdx.x >> 5, lane = threadIdx.x & 31;

    // phase A: row sums (warp handles 4 rows), 6-load front batch per row
    #pragma unroll
    for (int rr = wid * 4; rr < wid * 4 + 4; rr++) {
        int i = r0 + rr;
        const uint4* mrow = reinterpret_cast<const uint4*>(g_M8[mat] + (size_t)i * KP);
        uint4 buf[6];
        #pragma unroll
        for (int t = 0; t < 6; t++) {
            int idx = lane + t * 32;
            if (idx < KC16) buf[t] = mrow[idx];
        }
        float acc = 0.0f;
        #pragma unroll
        for (int t = 0; t < 6; t++) {
            int idx = lane + t * 32;
            if (idx < KC16) {
                float m[16]; unpack16f8(buf[t], m);
                #pragma unroll
                for (int k = 0; k < 16; k += 4) {
                    float4 v = *reinterpret_cast<const float4*>(&sv[idx * 16 + k]);
                    acc += m[k] * v.x + m[k + 1] * v.y + m[k + 2] * v.z + m[k + 3] * v.w;
                }
            }
        }
        acc = warp_red(acc);
        if (lane == 0) {
            float p = acc * (1.0f / (float)K_DIM);
            sp[rr] = frcp(p) * (1.0f / (float)B_DIM);   // u_i
        }
    }
    __syncthreads();

    // phase B: column partials over same 32 rows (one 16-elem chunk per thread)
    float* cn = g_c[mat][iter + 1];
    const int c16 = threadIdx.x;
    if (c16 < KC16) {
        float a[16];
        #pragma unroll
        for (int k = 0; k < 16; k++) a[k] = 0.0f;
        #pragma unroll 8
        for (int r = 0; r < 32; r++) {
            uint4 ch = *(reinterpret_cast<const uint4*>(g_M8[mat] + (size_t)(r0 + r) * KP) + c16);
            float m[16]; unpack16f8(ch, m);
            float u = sp[r];
            #pragma unroll
            for (int k = 0; k < 16; k++) a[k] += m[k] * u;
        }
        #pragma unroll
        for (int k = 0; k < 16; k++)
            atomicAdd(&cn[c16 * 16 + k], a[k]);
    }
}

// ---------------- iter-2 row pass + cross terms: fp8 M, 32 rows/block, grid (128,2) ----------------
__global__ void __launch_bounds__(256) rowcross_kernel() {
    const int m = blockIdx.y, o = 1 - m;
    const int r0 = blockIdx.x * 32;
    __shared__ float sv[KP];
    {
        const float4* c4 = reinterpret_cast<const float4*>(g_c[m][2]);
        for (int j4 = threadIdx.x; j4 < KP / 4; j4 += 256) {
            float4 c = c4[j4];
            *reinterpret_cast<float4*>(&sv[j4 * 4]) =
                make_float4(frcp(c.x), frcp(c.y), frcp(c.z), frcp(c.w));
        }
    }
    __syncthreads();
    const int wid = threadIdx.x >> 5, lane = threadIdx.x & 31;
    #pragma unroll
    for (int rr = wid * 4; rr < wid * 4 + 4; rr++) {
        int i = r0 + rr;
        const uint4* mrow = reinterpret_cast<const uint4*>(g_M8[m] + (size_t)i * KP);
        const uint4* srow = reinterpret_cast<const uint4*>(g_scores[o] + (size_t)i * KP);
        float ap = 0.0f, at = 0.0f;
        #pragma unroll
        for (int t0 = 0; t0 < 6; t0 += 3) {
            uint4 mb[3], sb[3][2];
            #pragma unroll
            for (int t = 0; t < 3; t++) {
                int idx = lane + (t0 + t) * 32;
                if (idx < KC16) {
                    mb[t] = mrow[idx];
                    sb[t][0] = srow[idx * 2];
                    sb[t][1] = srow[idx * 2 + 1];
                }
            }
            #pragma unroll
            for (int t = 0; t < 3; t++) {
                int idx = lane + (t0 + t) * 32;
                if (idx < KC16) {
                    float mm[16], x[16];
                    unpack16f8(mb[t], mm);
                    unpack8b(sb[t][0], x);
                    unpack8b(sb[t][1], x + 8);
                    #pragma unroll
                    for (int k = 0; k < 16; k += 4) {
                        float4 v = *reinterpret_cast<const float4*>(&sv[idx * 16 + k]);
                        float e0 = mm[k] * v.x, e1 = mm[k + 1] * v.y;
                        float e2 = mm[k + 2] * v.z, e3 = mm[k + 3] * v.w;
                        ap += (e0 + e1) + (e2 + e3);
                        at += e0 * x[k] + e1 * x[k + 1] + e2 * x[k + 2] + e3 * x[k + 3];
                    }
                }
            }
        }
        ap = warp_red(ap); at = warp_red(at);
        if (lane == 0) {
            g_p[m][2][i] = ap * (1.0f / (float)K_DIM);
            g_t[m][i]    = at * (1.0f / (float)K_DIM);
        }
    }
}

// ---------------- finalize ----------------
__global__ void finalize_kernel(float* out) {
    float a = 0.0f, l = 0.0f;
    for (int i = threadIdx.x; i < B_DIM; i += blockDim.x) {
        a += g_t[0][i] / ((float)B_DIM * g_p[0][2][i])
           + g_t[1][i] / ((float)B_DIM * g_p[1][2][i]);
        l += __logf(g_E[0][i]) + __logf(g_E[1][i]);
    }
    a = warp_red(a); l = warp_red(l);
    __shared__ float sa[8], sl[8];
    int lane = threadIdx.x & 31, wid = threadIdx.x >> 5;
    if (lane == 0) { sa[wid] = a; sl[wid] = l; }
    __syncthreads();
    if (threadIdx.x == 0) {
        float ta = 0.f, tl = 0.f;
        for (int w = 0; w < 8; w++) { ta += sa[w]; tl += sl[w]; }
        float loss = -0.5f * (ta / ((float)B_DIM * TEMP)
                              - tl / ((float)B_DIM * (float)B_DIM));
        out[0] = loss;
    }
}

// ---------------- launch (single stream) ----------------
extern "C" void kernel_launch(void* const* d_in, const int* in_sizes, int n_in,
                              void* d_out, int out_size) {
    const float* z1 = (const float*)d_in[0];
    const float* z2 = (const float*)d_in[1];
    const float* W  = (const float*)d_in[2];
    float* out = (float*)d_out;

    cudaFuncSetAttribute(gemm_kernel, cudaFuncAttributeMaxDynamicSharedMemorySize, DYN_SMEM);

    cvt_kernel<<<2048, 256>>>(z1, z2, W);

    dim3 ggrid(24, 32, 2);
    gemm_kernel<<<ggrid, 256, DYN_SMEM>>>();

    fused_pass<<<dim3(128, 2), 256>>>(0);     // p0 + c1
    fused_pass<<<dim3(128, 2), 256>>>(1);     // p1 + c2
    rowcross_kernel<<<dim3(128, 2), 256>>>(); // p2 + t
    finalize_kernel<<<1, 256>>>(out);
}